// round 12
// baseline (speedup 1.0000x reference)
#include <cuda_runtime.h>
#include <cuda_bf16.h>
#include <math.h>

#define N_NODES 50000
#define DIM     64
#define NHEAD   8
#define NEDGE   800000
#define NEG_SLOPE 0.2f

#define SCAN_BLK  1024
#define SCAN_NBLK ((N_NODES + SCAN_BLK - 1) / SCAN_BLK)   // 49

// Scratch (device globals). INVARIANT: g_deg zero at module load and re-zeroed
// by fill_kernel each call.
__device__ float g_sdst[N_NODES * NHEAD];
__device__ float g_ssrc[N_NODES * NHEAD];
__device__ int   g_deg[N_NODES];
__device__ int   g_row[N_NODES + 1];
__device__ int   g_cursor[N_NODES];
__device__ int   g_csr_src[NEDGE];
__device__ float g_csr_ex[(size_t)NEDGE * NHEAD];

__device__ __forceinline__ float lrelu(float v) {
    return v >= 0.0f ? v : NEG_SLOPE * v;
}

// ---------------------------------------------------------------------------
// Kernel 1: per-node scores (warp computes 2 nodes) + fused degree histogram.
// Reduction uses a halving tree (30 shfl vs 64): after 4 stages lane `sub`
// holds exactly score index c = sub for its node.
__global__ void scores_hist_kernel(const float* __restrict__ h_t,
                                   const float* __restrict__ att,
                                   const int* __restrict__ ei) {
    __shared__ float s_att[NHEAD * 2 * DIM];
    for (int i = threadIdx.x; i < NHEAD * 2 * DIM; i += blockDim.x)
        s_att[i] = att[i];
    __syncthreads();

    int idx = blockIdx.x * blockDim.x + threadIdx.x;
    if (idx >= NEDGE) return;

    atomicAdd(&g_deg[ei[NEDGE + idx]], 1);

    int lane = threadIdx.x & 31;
    int half = lane >> 4;
    int sub  = lane & 15;
    int n = (idx >> 5) * 2 + half;

    const float4 x = ((const float4*)(h_t + (size_t)n * DIM))[sub];

    // vals[c]: c&7 = head, c>>3 = is_src
    float vals[16];
#pragma unroll
    for (int c = 0; c < 16; c++) {
        const float4 a = *(const float4*)(s_att + (c & 7) * 128 + (c >> 3) * 64 + sub * 4);
        vals[c] = x.x * a.x + x.y * a.y + x.z * a.z + x.w * a.w;
    }
    // halving tree over the 16 lanes of this half (xor<16 stays in-half).
    // At stage o, lane keeps the half of indices whose bit==(sub&o).
    int cnt = 16;
#pragma unroll
    for (int o = 8; o >= 1; o >>= 1) {
        bool hi = (sub & o) != 0;
        int hc = cnt >> 1;
#pragma unroll
        for (int i = 0; i < 8; i++) {          // bounded by max hc
            if (i < hc) {
                float mine = hi ? vals[i] : vals[i + hc];
                float keep = hi ? vals[i + hc] : vals[i];
                float recv = __shfl_xor_sync(0xffffffffu, mine, o);
                vals[i] = keep + recv;
            }
        }
        cnt = hc;
    }
    // lane sub holds score index c=sub: c<8 -> sdst head c, else ssrc head c-8
    if (sub < 8) g_sdst[n * NHEAD + sub]       = vals[0];
    else         g_ssrc[n * NHEAD + (sub - 8)] = vals[0];
}

// ---------------------------------------------------------------------------
// Kernel 2: single-kernel scan; each block self-computes its prefix.
__global__ void scan_kernel() {
    __shared__ int sh[SCAN_BLK];
    __shared__ int red[32];
    __shared__ int s_boff;
    int t = threadIdx.x;
    int bid = blockIdx.x;

    int limit = bid * SCAN_BLK;
    int acc = 0;
    for (int i = t; i < limit; i += SCAN_BLK) acc += g_deg[i];
#pragma unroll
    for (int o = 16; o > 0; o >>= 1)
        acc += __shfl_down_sync(0xffffffffu, acc, o);
    if ((t & 31) == 0) red[t >> 5] = acc;
    __syncthreads();
    if (t < 32) {
        int w = red[t];
#pragma unroll
        for (int o = 16; o > 0; o >>= 1)
            w += __shfl_down_sync(0xffffffffu, w, o);
        if (t == 0) s_boff = w;
    }

    int i = bid * SCAN_BLK + t;
    int d = (i < N_NODES) ? g_deg[i] : 0;
    sh[t] = d;
    __syncthreads();
    for (int o = 1; o < SCAN_BLK; o <<= 1) {
        int u = (t >= o) ? sh[t - o] : 0;
        __syncthreads();
        sh[t] += u;
        __syncthreads();
    }
    if (i < N_NODES) {
        int excl = s_boff + sh[t] - d;
        g_row[i] = excl;
        g_cursor[i] = excl;
    }
    if (i == N_NODES - 1) g_row[N_NODES] = NEDGE;
}

// ---------------------------------------------------------------------------
// Kernel 3: fill CSR + per-edge exp for 8 heads; 4 edges per thread for MLP.
__global__ void fill_kernel(const int* __restrict__ ei) {
    int tid = blockIdx.x * blockDim.x + threadIdx.x;
    if (tid < N_NODES) g_deg[tid] = 0;
    if (tid >= NEDGE / 4) return;

    const int4 src4 = ((const int4*)ei)[tid];
    const int4 dst4 = ((const int4*)(ei + NEDGE))[tid];
    int srcs[4] = {src4.x, src4.y, src4.z, src4.w};
    int dsts[4] = {dst4.x, dst4.y, dst4.z, dst4.w};

    int ps[4];
#pragma unroll
    for (int k = 0; k < 4; k++)
        ps[k] = atomicAdd(&g_cursor[dsts[k]], 1);

    float4 d0[4], d1[4], s0[4], s1[4];
#pragma unroll
    for (int k = 0; k < 4; k++) {
        const float4* pd = (const float4*)(g_sdst + dsts[k] * NHEAD);
        const float4* pp = (const float4*)(g_ssrc + srcs[k] * NHEAD);
        d0[k] = pd[0]; d1[k] = pd[1];
        s0[k] = pp[0]; s1[k] = pp[1];
    }

#pragma unroll
    for (int k = 0; k < 4; k++) {
        float4 e0, e1;
        e0.x = __expf(lrelu(d0[k].x + s0[k].x));
        e0.y = __expf(lrelu(d0[k].y + s0[k].y));
        e0.z = __expf(lrelu(d0[k].z + s0[k].z));
        e0.w = __expf(lrelu(d0[k].w + s0[k].w));
        e1.x = __expf(lrelu(d1[k].x + s1[k].x));
        e1.y = __expf(lrelu(d1[k].y + s1[k].y));
        e1.z = __expf(lrelu(d1[k].z + s1[k].z));
        e1.w = __expf(lrelu(d1[k].w + s1[k].w));
        g_csr_src[ps[k]] = srcs[k];
        float4* pe = (float4*)(g_csr_ex + (size_t)ps[k] * NHEAD);
        pe[0] = e0;
        pe[1] = e1;
    }
}

// ---------------------------------------------------------------------------
// Kernel 4: aggregation + normalize + ELU. One warp per node.
// lane (h=lane>>2, q=lane&3) reads bytes {0,16,128,144} at rowbase + q*32.
// SOFTWARE PIPELINE: pair p's loads are issued before pair p-1's FMAs, so the
// ~240cyc L2 latency of the random h_t gathers overlaps with compute.
// launch_bounds(128,5) -> ~102 reg budget for the double buffer.
__device__ __forceinline__ void acc_pair(float4& a0, float4& a1, float4& a2, float4& a3,
                                         float& denom, float e0, float e1,
                                         const float4& xa0, const float4& xa1,
                                         const float4& xa2, const float4& xa3,
                                         const float4& xb0, const float4& xb1,
                                         const float4& xb2, const float4& xb3) {
    denom += e0 + e1;
    a0.x += e0*xa0.x; a0.y += e0*xa0.y; a0.z += e0*xa0.z; a0.w += e0*xa0.w;
    a1.x += e0*xa1.x; a1.y += e0*xa1.y; a1.z += e0*xa1.z; a1.w += e0*xa1.w;
    a2.x += e0*xa2.x; a2.y += e0*xa2.y; a2.z += e0*xa2.z; a2.w += e0*xa2.w;
    a3.x += e0*xa3.x; a3.y += e0*xa3.y; a3.z += e0*xa3.z; a3.w += e0*xa3.w;
    a0.x += e1*xb0.x; a0.y += e1*xb0.y; a0.z += e1*xb0.z; a0.w += e1*xb0.w;
    a1.x += e1*xb1.x; a1.y += e1*xb1.y; a1.z += e1*xb1.z; a1.w += e1*xb1.w;
    a2.x += e1*xb2.x; a2.y += e1*xb2.y; a2.z += e1*xb2.z; a2.w += e1*xb2.w;
    a3.x += e1*xb3.x; a3.y += e1*xb3.y; a3.z += e1*xb3.z; a3.w += e1*xb3.w;
}

__global__ void __launch_bounds__(128, 5)
node_agg_kernel(const float* __restrict__ h_t, float* __restrict__ out) {
    int warp = (blockIdx.x * blockDim.x + threadIdx.x) >> 5;
    if (warp >= N_NODES) return;
    int lane = threadIdx.x & 31;
    int n = warp;
    int rs = g_row[n];
    int re = g_row[n + 1];

    int h = lane >> 2;
    int q = lane & 3;
    const char* hbase = (const char*)h_t + q * 32;   // + s*256 per edge

    float4 a0 = make_float4(0.f, 0.f, 0.f, 0.f);
    float4 a1 = a0, a2 = a0, a3 = a0;
    float denom = 0.0f;

    for (int base = rs; base < re; base += 32) {
        int cnt = re - base; if (cnt > 32) cnt = 32;
        int s = (lane < cnt) ? g_csr_src[base + lane] : 0;
        const char* exp0 = (const char*)(g_csr_ex + (size_t)base * NHEAD + h);

        int npairs = cnt >> 1;
        if (npairs > 0) {
            // prologue: load pair 0
            int s0 = __shfl_sync(0xffffffffu, s, 0);
            int s1 = __shfl_sync(0xffffffffu, s, 1);
            float e0 = *(const float*)(exp0);
            float e1 = *(const float*)(exp0 + 32);
            const char* r0 = hbase + ((size_t)s0 << 8);
            const char* r1 = hbase + ((size_t)s1 << 8);
            float4 xa0 = *(const float4*)(r0);
            float4 xa1 = *(const float4*)(r0 + 16);
            float4 xa2 = *(const float4*)(r0 + 128);
            float4 xa3 = *(const float4*)(r0 + 144);
            float4 xb0 = *(const float4*)(r1);
            float4 xb1 = *(const float4*)(r1 + 16);
            float4 xb2 = *(const float4*)(r1 + 128);
            float4 xb3 = *(const float4*)(r1 + 144);

#pragma unroll 2
            for (int p = 1; p < npairs; p++) {
                int j = p * 2;
                // issue next pair's loads FIRST
                int t0 = __shfl_sync(0xffffffffu, s, j);
                int t1 = __shfl_sync(0xffffffffu, s, j + 1);
                float f0 = *(const float*)(exp0 + (size_t)j * 32);
                float f1 = *(const float*)(exp0 + (size_t)j * 32 + 32);
                const char* u0 = hbase + ((size_t)t0 << 8);
                const char* u1 = hbase + ((size_t)t1 << 8);
                float4 ya0 = *(const float4*)(u0);
                float4 ya1 = *(const float4*)(u0 + 16);
                float4 ya2 = *(const float4*)(u0 + 128);
                float4 ya3 = *(const float4*)(u0 + 144);
                float4 yb0 = *(const float4*)(u1);
                float4 yb1 = *(const float4*)(u1 + 16);
                float4 yb2 = *(const float4*)(u1 + 128);
                float4 yb3 = *(const float4*)(u1 + 144);

                // consume current pair while next pair's loads are in flight
                acc_pair(a0, a1, a2, a3, denom, e0, e1,
                         xa0, xa1, xa2, xa3, xb0, xb1, xb2, xb3);

                // roll buffers (renamed away by unroll-2)
                e0 = f0; e1 = f1;
                xa0 = ya0; xa1 = ya1; xa2 = ya2; xa3 = ya3;
                xb0 = yb0; xb1 = yb1; xb2 = yb2; xb3 = yb3;
            }
            // epilogue: consume last pair
            acc_pair(a0, a1, a2, a3, denom, e0, e1,
                     xa0, xa1, xa2, xa3, xb0, xb1, xb2, xb3);
        }
        if (cnt & 1) {
            int j = cnt - 1;
            int sj = __shfl_sync(0xffffffffu, s, j);
            float ex = *(const float*)(exp0 + (size_t)j * 32);
            const char* r = hbase + ((size_t)sj << 8);
            float4 x0 = *(const float4*)(r);
            float4 x1 = *(const float4*)(r + 16);
            float4 x2 = *(const float4*)(r + 128);
            float4 x3 = *(const float4*)(r + 144);
            denom += ex;
            a0.x += ex*x0.x; a0.y += ex*x0.y; a0.z += ex*x0.z; a0.w += ex*x0.w;
            a1.x += ex*x1.x; a1.y += ex*x1.y; a1.z += ex*x1.z; a1.w += ex*x1.w;
            a2.x += ex*x2.x; a2.y += ex*x2.y; a2.z += ex*x2.z; a2.w += ex*x2.w;
            a3.x += ex*x3.x; a3.y += ex*x3.y; a3.z += ex*x3.z; a3.w += ex*x3.w;
        }
    }

    float inv = (re > rs) ? 1.0f / denom : 0.0f;

    char* orow = (char*)out + ((size_t)n * (NHEAD * DIM) + h * DIM) * 4 + q * 32;
    float4 r4[4] = {a0, a1, a2, a3};
    const int offs[4] = {0, 16, 128, 144};
#pragma unroll
    for (int k = 0; k < 4; k++) {
        float4 x = r4[k];
        x.x *= inv; x.y *= inv; x.z *= inv; x.w *= inv;
        x.x = x.x > 0.f ? x.x : (__expf(x.x) - 1.0f);
        x.y = x.y > 0.f ? x.y : (__expf(x.y) - 1.0f);
        x.z = x.z > 0.f ? x.z : (__expf(x.z) - 1.0f);
        x.w = x.w > 0.f ? x.w : (__expf(x.w) - 1.0f);
        *(float4*)(orow + offs[k]) = x;
    }
}

// ---------------------------------------------------------------------------
extern "C" void kernel_launch(void* const* d_in, const int* in_sizes, int n_in,
                              void* d_out, int out_size) {
    const float* h_t = (const float*)d_in[0];
    const int*   ei  = (const int*)d_in[1];
    const float* att = (const float*)d_in[2];
    float*       out = (float*)d_out;

    scores_hist_kernel<<<(NEDGE + 255) / 256, 256>>>(h_t, att, ei);  // 1
    scan_kernel<<<SCAN_NBLK, SCAN_BLK>>>();                          // 2
    fill_kernel<<<(NEDGE / 4 + 255) / 256, 256>>>(ei);               // 3
    int blocks = (N_NODES * 32 + 127) / 128;
    node_agg_kernel<<<blocks, 128>>>(h_t, out);                      // 4 (ncu)
}

// round 13
// speedup vs baseline: 1.1776x; 1.1776x over previous
#include <cuda_runtime.h>
#include <cuda_bf16.h>
#include <math.h>

#define N_NODES 50000
#define DIM     64
#define NHEAD   8
#define NEDGE   800000
#define NEG_SLOPE 0.2f

#define SCAN_BLK  1024
#define SCAN_NBLK ((N_NODES + SCAN_BLK - 1) / SCAN_BLK)   // 49

// Scratch (device globals). INVARIANT: g_deg zero at module load and re-zeroed
// by fill_kernel each call.
__device__ float g_sdst[N_NODES * NHEAD];
__device__ float g_ssrc[N_NODES * NHEAD];
__device__ int   g_deg[N_NODES];
__device__ int   g_row[N_NODES + 1];
__device__ int   g_cursor[N_NODES];
__device__ int   g_csr_src[NEDGE];
__device__ float g_csr_ex[(size_t)NEDGE * NHEAD];

__device__ __forceinline__ float lrelu(float v) {
    return v >= 0.0f ? v : NEG_SLOPE * v;
}

// ---------------------------------------------------------------------------
// Kernel 1: per-node scores (warp computes 2 nodes) + fused degree histogram.
// Halving-tree reduction (30 shfl): lane `sub` ends holding score index c=sub.
__global__ void scores_hist_kernel(const float* __restrict__ h_t,
                                   const float* __restrict__ att,
                                   const int* __restrict__ ei) {
    __shared__ float s_att[NHEAD * 2 * DIM];
    for (int i = threadIdx.x; i < NHEAD * 2 * DIM; i += blockDim.x)
        s_att[i] = att[i];
    __syncthreads();

    int idx = blockIdx.x * blockDim.x + threadIdx.x;
    if (idx >= NEDGE) return;

    atomicAdd(&g_deg[ei[NEDGE + idx]], 1);

    int lane = threadIdx.x & 31;
    int half = lane >> 4;
    int sub  = lane & 15;
    int n = (idx >> 5) * 2 + half;

    const float4 x = ((const float4*)(h_t + (size_t)n * DIM))[sub];

    float vals[16];
#pragma unroll
    for (int c = 0; c < 16; c++) {
        const float4 a = *(const float4*)(s_att + (c & 7) * 128 + (c >> 3) * 64 + sub * 4);
        vals[c] = x.x * a.x + x.y * a.y + x.z * a.z + x.w * a.w;
    }
    int cnt = 16;
#pragma unroll
    for (int o = 8; o >= 1; o >>= 1) {
        bool hi = (sub & o) != 0;
        int hc = cnt >> 1;
#pragma unroll
        for (int i = 0; i < 8; i++) {
            if (i < hc) {
                float mine = hi ? vals[i] : vals[i + hc];
                float keep = hi ? vals[i + hc] : vals[i];
                float recv = __shfl_xor_sync(0xffffffffu, mine, o);
                vals[i] = keep + recv;
            }
        }
        cnt = hc;
    }
    if (sub < 8) g_sdst[n * NHEAD + sub]       = vals[0];
    else         g_ssrc[n * NHEAD + (sub - 8)] = vals[0];
}

// ---------------------------------------------------------------------------
// Kernel 2: single-kernel scan; each block self-computes its prefix.
__global__ void scan_kernel() {
    __shared__ int sh[SCAN_BLK];
    __shared__ int red[32];
    __shared__ int s_boff;
    int t = threadIdx.x;
    int bid = blockIdx.x;

    int limit = bid * SCAN_BLK;
    int acc = 0;
    for (int i = t; i < limit; i += SCAN_BLK) acc += g_deg[i];
#pragma unroll
    for (int o = 16; o > 0; o >>= 1)
        acc += __shfl_down_sync(0xffffffffu, acc, o);
    if ((t & 31) == 0) red[t >> 5] = acc;
    __syncthreads();
    if (t < 32) {
        int w = red[t];
#pragma unroll
        for (int o = 16; o > 0; o >>= 1)
            w += __shfl_down_sync(0xffffffffu, w, o);
        if (t == 0) s_boff = w;
    }

    int i = bid * SCAN_BLK + t;
    int d = (i < N_NODES) ? g_deg[i] : 0;
    sh[t] = d;
    __syncthreads();
    for (int o = 1; o < SCAN_BLK; o <<= 1) {
        int u = (t >= o) ? sh[t - o] : 0;
        __syncthreads();
        sh[t] += u;
        __syncthreads();
    }
    if (i < N_NODES) {
        int excl = s_boff + sh[t] - d;
        g_row[i] = excl;
        g_cursor[i] = excl;
    }
    if (i == N_NODES - 1) g_row[N_NODES] = NEDGE;
}

// ---------------------------------------------------------------------------
// Kernel 3: fill CSR + per-edge exp for 8 heads; 4 edges per thread for MLP.
__global__ void fill_kernel(const int* __restrict__ ei) {
    int tid = blockIdx.x * blockDim.x + threadIdx.x;
    if (tid < N_NODES) g_deg[tid] = 0;
    if (tid >= NEDGE / 4) return;

    const int4 src4 = ((const int4*)ei)[tid];
    const int4 dst4 = ((const int4*)(ei + NEDGE))[tid];
    int srcs[4] = {src4.x, src4.y, src4.z, src4.w};
    int dsts[4] = {dst4.x, dst4.y, dst4.z, dst4.w};

    int ps[4];
#pragma unroll
    for (int k = 0; k < 4; k++)
        ps[k] = atomicAdd(&g_cursor[dsts[k]], 1);

    float4 d0[4], d1[4], s0[4], s1[4];
#pragma unroll
    for (int k = 0; k < 4; k++) {
        const float4* pd = (const float4*)(g_sdst + dsts[k] * NHEAD);
        const float4* pp = (const float4*)(g_ssrc + srcs[k] * NHEAD);
        d0[k] = pd[0]; d1[k] = pd[1];
        s0[k] = pp[0]; s1[k] = pp[1];
    }

#pragma unroll
    for (int k = 0; k < 4; k++) {
        float4 e0, e1;
        e0.x = __expf(lrelu(d0[k].x + s0[k].x));
        e0.y = __expf(lrelu(d0[k].y + s0[k].y));
        e0.z = __expf(lrelu(d0[k].z + s0[k].z));
        e0.w = __expf(lrelu(d0[k].w + s0[k].w));
        e1.x = __expf(lrelu(d1[k].x + s1[k].x));
        e1.y = __expf(lrelu(d1[k].y + s1[k].y));
        e1.z = __expf(lrelu(d1[k].z + s1[k].z));
        e1.w = __expf(lrelu(d1[k].w + s1[k].w));
        g_csr_src[ps[k]] = srcs[k];
        float4* pe = (float4*)(g_csr_ex + (size_t)ps[k] * NHEAD);
        pe[0] = e0;
        pe[1] = e1;
    }
}

// ---------------------------------------------------------------------------
// Kernel 4: aggregation + normalize + ELU. One warp per node.
// LANE-OWNS-DIMS: lane owns dims {2*lane, 2*lane+1} for ALL 8 heads.
// Per edge: one LDG.64 (256B distinct across warp = 2 wavefronts, vs 16
// duplicated before) + 2 broadcast LDS.128 for the 8 ex values (staged per
// 32-edge chunk in smem). Denom via per-lane partials + one butterfly/node.
__global__ void __launch_bounds__(128, 8)
node_agg_kernel(const float* __restrict__ h_t, float* __restrict__ out) {
    __shared__ float s_ex[4][32 * NHEAD];          // 1KB per warp
    int wib  = threadIdx.x >> 5;
    int warp = (blockIdx.x * blockDim.x + threadIdx.x) >> 5;
    if (warp >= N_NODES) return;
    int lane = threadIdx.x & 31;
    int n = warp;
    int rs = g_row[n];
    int re = g_row[n + 1];

    const char* hbase = (const char*)h_t + lane * 8;   // + s*256 per edge

    float2 acc[8];
#pragma unroll
    for (int k = 0; k < 8; k++) acc[k] = make_float2(0.f, 0.f);
    float dsum[8];
#pragma unroll
    for (int k = 0; k < 8; k++) dsum[k] = 0.f;

    float* exrow = s_ex[wib];

    for (int base = rs; base < re; base += 32) {
        int cnt = re - base; if (cnt > 32) cnt = 32;

        // stage: lane i loads edge i's src + 8 ex values
        int s = 0;
        float4 exa = make_float4(0.f, 0.f, 0.f, 0.f), exb = exa;
        if (lane < cnt) {
            s = g_csr_src[base + lane];
            const float4* pe = (const float4*)(g_csr_ex + (size_t)(base + lane) * NHEAD);
            exa = pe[0]; exb = pe[1];
        }
        // per-lane denom partials (zero for inactive lanes)
        dsum[0] += exa.x; dsum[1] += exa.y; dsum[2] += exa.z; dsum[3] += exa.w;
        dsum[4] += exb.x; dsum[5] += exb.y; dsum[6] += exb.z; dsum[7] += exb.w;

        __syncwarp();
        float4* sw = (float4*)(exrow + lane * NHEAD);
        sw[0] = exa; sw[1] = exb;
        __syncwarp();

#pragma unroll 2
        for (int j = 0; j < cnt; j++) {
            int sj = __shfl_sync(0xffffffffu, s, j);
            float4 e0 = *(const float4*)(exrow + j * NHEAD);
            float4 e1 = *(const float4*)(exrow + j * NHEAD + 4);
            float2 v = *(const float2*)(hbase + ((size_t)sj << 8));
            acc[0].x += e0.x * v.x; acc[0].y += e0.x * v.y;
            acc[1].x += e0.y * v.x; acc[1].y += e0.y * v.y;
            acc[2].x += e0.z * v.x; acc[2].y += e0.z * v.y;
            acc[3].x += e0.w * v.x; acc[3].y += e0.w * v.y;
            acc[4].x += e1.x * v.x; acc[4].y += e1.x * v.y;
            acc[5].x += e1.y * v.x; acc[5].y += e1.y * v.y;
            acc[6].x += e1.z * v.x; acc[6].y += e1.z * v.y;
            acc[7].x += e1.w * v.x; acc[7].y += e1.w * v.y;
        }
    }

    // denom: butterfly-reduce the 8 partials across all 32 lanes
#pragma unroll
    for (int o = 16; o > 0; o >>= 1) {
#pragma unroll
        for (int k = 0; k < 8; k++)
            dsum[k] += __shfl_xor_sync(0xffffffffu, dsum[k], o);
    }

    bool nz = (re > rs);
    float* orow = out + (size_t)n * (NHEAD * DIM) + lane * 2;
#pragma unroll
    for (int k = 0; k < 8; k++) {
        float inv = nz ? 1.0f / dsum[k] : 0.f;      // zero-degree -> zeros
        float vx = acc[k].x * inv;
        float vy = acc[k].y * inv;
        vx = vx > 0.f ? vx : (__expf(vx) - 1.0f);
        vy = vy > 0.f ? vy : (__expf(vy) - 1.0f);
        *(float2*)(orow + k * DIM) = make_float2(vx, vy);
    }
}

// ---------------------------------------------------------------------------
extern "C" void kernel_launch(void* const* d_in, const int* in_sizes, int n_in,
                              void* d_out, int out_size) {
    const float* h_t = (const float*)d_in[0];
    const int*   ei  = (const int*)d_in[1];
    const float* att = (const float*)d_in[2];
    float*       out = (float*)d_out;

    scores_hist_kernel<<<(NEDGE + 255) / 256, 256>>>(h_t, att, ei);  // 1
    scan_kernel<<<SCAN_NBLK, SCAN_BLK>>>();                          // 2
    fill_kernel<<<(NEDGE / 4 + 255) / 256, 256>>>(ei);               // 3
    int blocks = (N_NODES * 32 + 127) / 128;
    node_agg_kernel<<<blocks, 128>>>(h_t, out);                      // 4 (ncu)
}